// round 5
// baseline (speedup 1.0000x reference)
#include <cuda_runtime.h>
#include <cstdint>
#include <math.h>

// Problem constants
#define Bb   256
#define Tt   1024
#define Hh   164
#define JH   82          // hidden per CTA (M-split across 2-CTA cluster)
#define QK   11          // k-pairs per octant (8*11 = 88 >= 82, padded)
#define RKO  3           // k-pairs in registers per octant
#define SKO  (QK - RKO)  // 8 smem k-pair slots
#define CT   656         // compute threads: 82 jj x 8 octants
#define NTH  672         // 21 warps (16 spare threads)
#define NCTA 128         // 64 clusters x 2

// shared memory layout (bytes)
#define OFF_WSM  0
#define SZ_WSM   (SKO * 4 * CT * 8)     // 167936: Wsm64[slot][gate][tid]
#define OFF_HQ   (OFF_WSM + SZ_WSM)
#define HBUF     (8 * 368)              // 2944 per parity (368B per octant, pad)
#define SZ_HQ    (2 * HBUF)
#define OFF_XQ   (OFF_HQ + SZ_HQ)
#define SZ_XQ    (2 * 8 * 16)           // x double-buffered [par][i][r]
#define OFF_PW   (OFF_XQ + SZ_XQ)
#define SZ_PW    (2 * 21 * 16)          // pred warp partials [par][w][r]
#define OFF_PR   (OFF_PW + SZ_PW)       // pown[2][4] then ppeer[2][4]
#define SZ_PR    64
#define OFF_WIH  (OFF_PR + SZ_PR)
#define SZ_WIH   (7 * 82 * 16)          // wih4[i-1][jj] = per-gate float4
#define OFF_B4   (OFF_WIH + SZ_WIH)
#define SZ_B4    (82 * 16)              // bias4[jj]
#define OFF_W04  (OFF_B4 + SZ_B4)
#define SZ_W04   (82 * 16)              // w_ih[:,0] per gate float4
#define OFF_WO   (OFF_W04 + SZ_W04)
#define SZ_WO    (82 * 4)               // wout[jj]
#define OFF_MBAR ((OFF_WO + SZ_WO + 7) & ~7)
#define SMEM_TOTAL (OFF_MBAR + 16)      // ~187 KB

typedef unsigned long long ull;

__device__ __forceinline__ float sigmoidf_(float v) {
    return 1.0f / (1.0f + expf(-v));
}
__device__ __forceinline__ ull pack2_(float a, float b) {
    ull r; asm("mov.b64 %0, {%1, %2};" : "=l"(r) : "f"(a), "f"(b)); return r;
}
__device__ __forceinline__ void unpack2_(ull v, float& a, float& b) {
    asm("mov.b64 {%0, %1}, %2;" : "=f"(a), "=f"(b) : "l"(v));
}
__device__ __forceinline__ void fma2_(ull& acc, ull a, ull b) {
    asm("fma.rn.f32x2 %0, %1, %2, %0;" : "+l"(acc) : "l"(a), "l"(b));
}
__device__ __forceinline__ void st_remote_f32(uint32_t local_addr, uint32_t peer, float v) {
    uint32_t ra;
    asm("mapa.shared::cluster.u32 %0, %1, %2;" : "=r"(ra) : "r"(local_addr), "r"(peer));
    asm volatile("st.shared::cluster.f32 [%0], %1;" :: "r"(ra), "f"(v) : "memory");
}
__device__ __forceinline__ void mbar_arrive_peer(uint32_t local_mbar, uint32_t peer) {
    asm volatile(
        "{\n\t.reg .b32 ra;\n\t"
        "mapa.shared::cluster.u32 ra, %0, %1;\n\t"
        "mbarrier.arrive.release.cluster.shared::cluster.b64 _, [ra];\n\t}"
        :: "r"(local_mbar), "r"(peer) : "memory");
}
__device__ __forceinline__ void mbar_wait(uint32_t mbar, uint32_t parity) {
    uint32_t done;
    asm volatile(
        "{\n\t.reg .pred p;\n\t"
        "mbarrier.try_wait.parity.acquire.cluster.shared::cta.b64 p, [%1], %2;\n\t"
        "selp.b32 %0, 1, 0, p;\n\t}"
        : "=r"(done) : "r"(mbar), "r"(parity) : "memory");
    while (!done) {
        asm volatile(
            "{\n\t.reg .pred p;\n\t"
            "mbarrier.try_wait.parity.acquire.cluster.shared::cta.b64 p, [%1], %2, 0x989680;\n\t"
            "selp.b32 %0, 1, 0, p;\n\t}"
            : "=r"(done) : "r"(mbar), "r"(parity) : "memory");
    }
}

extern "C" __global__ void __launch_bounds__(NTH, 1) __cluster_dims__(2, 1, 1)
lstm_anom_kernel(const float* __restrict__ x,
                 const float* __restrict__ Wih,
                 const float* __restrict__ Whh,
                 const float* __restrict__ bih,
                 const float* __restrict__ bhh,
                 const float* __restrict__ Wout,
                 const float* __restrict__ bout,
                 float* __restrict__ out)
{
    extern __shared__ char smem[];
    ull*    Wsm64 = (ull*)(smem + OFF_WSM);
    float*  xqf   = (float*)(smem + OFF_XQ);
    float*  pwf   = (float*)(smem + OFF_PW);
    float*  prf   = (float*)(smem + OFF_PR);      // [par*4+r] own, [8+par*4+r] peer
    float4* wih4  = (float4*)(smem + OFF_WIH);
    float4* b4    = (float4*)(smem + OFF_B4);
    float4* w04   = (float4*)(smem + OFF_W04);
    float*  wo    = (float*)(smem + OFF_WO);

    const int tid       = threadIdx.x;
    const uint32_t rank = (uint32_t)(blockIdx.x & 1);
    const uint32_t peer = rank ^ 1u;
    const int cluster   = blockIdx.x >> 1;
    const int row0      = cluster * 4;

    const uint32_t smem_b = (uint32_t)__cvta_generic_to_shared(smem);
    const uint32_t mbar_b = smem_b + OFF_MBAR;

    // ---------- one-time init ----------
    const int jj  = tid >> 3;      // 0..81 (compute threads)
    const int oct = tid & 7;       // k-octant
    ull wreg[RKO][4];
    if (tid < CT) {
        int R0 = 0 * Hh + (int)rank * JH + jj;
        int R1 = 1 * Hh + (int)rank * JH + jj;
        int R2 = 2 * Hh + (int)rank * JH + jj;
        int R3 = 3 * Hh + (int)rank * JH + jj;
        const ull* whh64 = (const ull*)Whh;
#pragma unroll
        for (int kk = 0; kk < QK; kk++) {
            int kp = oct * QK + kk;
            ull v0 = (kp < 82) ? whh64[(size_t)R0 * 82 + kp] : 0ull;
            ull v1 = (kp < 82) ? whh64[(size_t)R1 * 82 + kp] : 0ull;
            ull v2 = (kp < 82) ? whh64[(size_t)R2 * 82 + kp] : 0ull;
            ull v3 = (kp < 82) ? whh64[(size_t)R3 * 82 + kp] : 0ull;
            if (kk < RKO) {
                wreg[kk][0] = v0; wreg[kk][1] = v1;
                wreg[kk][2] = v2; wreg[kk][3] = v3;
            } else {
                int s = kk - RKO;
                Wsm64[((s * 4 + 0) * CT) + tid] = v0;
                Wsm64[((s * 4 + 1) * CT) + tid] = v1;
                Wsm64[((s * 4 + 2) * CT) + tid] = v2;
                Wsm64[((s * 4 + 3) * CT) + tid] = v3;
            }
        }
        if (oct == 0) {
#pragma unroll
            for (int i = 1; i < 8; i++)
                wih4[(i - 1) * 82 + jj] = make_float4(
                    Wih[R0 * 8 + i], Wih[R1 * 8 + i], Wih[R2 * 8 + i], Wih[R3 * 8 + i]);
            b4[jj]  = make_float4(bih[R0] + bhh[R0], bih[R1] + bhh[R1],
                                  bih[R2] + bhh[R2], bih[R3] + bhh[R3]);
            w04[jj] = make_float4(Wih[R0 * 8], Wih[R1 * 8], Wih[R2 * 8], Wih[R3 * 8]);
            wo[jj]  = Wout[(int)rank * JH + jj];
        }
    }
    for (int idx = tid; idx < (SZ_HQ / 4); idx += NTH)
        ((float*)(smem + OFF_HQ))[idx] = 0.f;
    for (int idx = tid; idx < (SZ_PW / 4); idx += NTH) pwf[idx] = 0.f;
    if (tid < 16) prf[tid] = 0.f;
    if (tid < 32) {
        int i = tid >> 2, r = tid & 3;
        xqf[(0 * 8 + i) * 4 + r] = x[((size_t)((row0 + r) * Tt)) * 8 + i];
    }
    if (tid == 0) {
        asm volatile("mbarrier.init.shared.b64 [%0], 4;" :: "r"(mbar_b) : "memory");
        asm volatile("mbarrier.init.shared.b64 [%0], 4;" :: "r"(mbar_b + 8) : "memory");
    }
    const float bout_r = bout[0];
    float c_r = 0.f;    // activation state for (jj, rmap(oct)), oct<4 lanes

    __syncthreads();
    asm volatile("barrier.cluster.arrive.aligned;" ::: "memory");
    asm volatile("barrier.cluster.wait.aligned;" ::: "memory");

    const int wid = tid >> 5, lane = tid & 31;
    const unsigned wm = (wid == 20) ? 0xffffu : 0xffffffffu;

    for (int t = 0; t < Tt; ++t) {
        const int cur = t & 1;
        const int nxt = cur ^ 1;

        if (t) mbar_wait(mbar_b + (uint32_t)(((t - 1) & 1) * 8), (uint32_t)(((t - 1) >> 1) & 1));

        if (tid < CT) {
            // ---- accumulator init: bias (oct 0) or x_i * W_ih (oct = i, 1..7) ----
            ull acc[16];   // [gate*4 + r], lo = even-k sum, hi = odd-k sum
            if (oct == 0) {
                float4 bb = b4[jj];
#pragma unroll
                for (int r = 0; r < 4; r++) {
                    acc[0 * 4 + r] = pack2_(bb.x, 0.f);
                    acc[1 * 4 + r] = pack2_(bb.y, 0.f);
                    acc[2 * 4 + r] = pack2_(bb.z, 0.f);
                    acc[3 * 4 + r] = pack2_(bb.w, 0.f);
                }
            } else {
                float4 xv = *(const float4*)(smem + OFF_XQ + (cur * 8 + oct) * 16);
                float4 wv = wih4[(oct - 1) * 82 + jj];
                acc[0]  = pack2_(wv.x * xv.x, 0.f); acc[1]  = pack2_(wv.x * xv.y, 0.f);
                acc[2]  = pack2_(wv.x * xv.z, 0.f); acc[3]  = pack2_(wv.x * xv.w, 0.f);
                acc[4]  = pack2_(wv.y * xv.x, 0.f); acc[5]  = pack2_(wv.y * xv.y, 0.f);
                acc[6]  = pack2_(wv.y * xv.z, 0.f); acc[7]  = pack2_(wv.y * xv.w, 0.f);
                acc[8]  = pack2_(wv.z * xv.x, 0.f); acc[9]  = pack2_(wv.z * xv.y, 0.f);
                acc[10] = pack2_(wv.z * xv.z, 0.f); acc[11] = pack2_(wv.z * xv.w, 0.f);
                acc[12] = pack2_(wv.w * xv.x, 0.f); acc[13] = pack2_(wv.w * xv.y, 0.f);
                acc[14] = pack2_(wv.w * xv.z, 0.f); acc[15] = pack2_(wv.w * xv.w, 0.f);
            }
            // ---- GEMV over own octant's 11 k-pairs ----
            const char* hbase = smem + OFF_HQ + cur * HBUF + oct * 368;
#pragma unroll
            for (int kk = 0; kk < QK; kk++) {
                ulonglong2 hA = *(const ulonglong2*)(hbase + kk * 32);       // r0, r1
                ulonglong2 hB = *(const ulonglong2*)(hbase + kk * 32 + 16);  // r2, r3
                ull w0, w1, w2, w3;
                if (kk < RKO) {
                    w0 = wreg[kk][0]; w1 = wreg[kk][1];
                    w2 = wreg[kk][2]; w3 = wreg[kk][3];
                } else {
                    int s = kk - RKO;
                    w0 = Wsm64[((s * 4 + 0) * CT) + tid];
                    w1 = Wsm64[((s * 4 + 1) * CT) + tid];
                    w2 = Wsm64[((s * 4 + 2) * CT) + tid];
                    w3 = Wsm64[((s * 4 + 3) * CT) + tid];
                }
                fma2_(acc[0],  w0, hA.x); fma2_(acc[1],  w0, hA.y);
                fma2_(acc[2],  w0, hB.x); fma2_(acc[3],  w0, hB.y);
                fma2_(acc[4],  w1, hA.x); fma2_(acc[5],  w1, hA.y);
                fma2_(acc[6],  w1, hB.x); fma2_(acc[7],  w1, hB.y);
                fma2_(acc[8],  w2, hA.x); fma2_(acc[9],  w2, hA.y);
                fma2_(acc[10], w2, hB.x); fma2_(acc[11], w2, hB.y);
                fma2_(acc[12], w3, hA.x); fma2_(acc[13], w3, hA.y);
                fma2_(acc[14], w3, hB.x); fma2_(acc[15], w3, hB.y);
            }
            // ---- compress to 16 floats ----
            float v[16];
#pragma unroll
            for (int s = 0; s < 16; s++) {
                float lo, hi; unpack2_(acc[s], lo, hi); v[s] = lo + hi;
            }
            // ---- reduce-scatter over 8 octants (16 shfls) ----
            const bool odd1 = (oct & 1);
#pragma unroll
            for (int g2 = 0; g2 < 4; g2++) {   // L1: xor 1 — split r01 / r23
                float sA = odd1 ? v[g2 * 4 + 0] : v[g2 * 4 + 2];
                float sB = odd1 ? v[g2 * 4 + 1] : v[g2 * 4 + 3];
                float rA = __shfl_xor_sync(wm, sA, 1);
                float rB = __shfl_xor_sync(wm, sB, 1);
                if (!odd1) { v[g2 * 4 + 0] += rA; v[g2 * 4 + 1] += rB; }
                else       { v[g2 * 4 + 2] += rA; v[g2 * 4 + 3] += rB; }
            }
            float w4g[4];
            const bool keepFirst = !(oct & 2);
#pragma unroll
            for (int g2 = 0; g2 < 4; g2++) {   // L2: xor 2 — split within pair
                float ua = odd1 ? v[g2 * 4 + 2] : v[g2 * 4 + 0];
                float ub = odd1 ? v[g2 * 4 + 3] : v[g2 * 4 + 1];
                float send = keepFirst ? ub : ua;
                float recv = __shfl_xor_sync(wm, send, 2);
                w4g[g2] = (keepFirst ? ua : ub) + recv;
            }
#pragma unroll
            for (int g2 = 0; g2 < 4; g2++)     // L3: xor 4 — final sum
                w4g[g2] += __shfl_xor_sync(wm, w4g[g2], 4);

            // ---- activation on oct<4 lanes: one (jj, r) each ----
            float p = 0.f;
            if (oct < 4) {
                const int r = (oct >> 1) | ((oct & 1) << 1);   // 0,2,1,3
                float xr = xqf[(cur * 8 + 0) * 4 + r];
                float x0 = xr;
                if (t > 0) {
                    float pred = prf[nxt * 4 + r] + prf[8 + nxt * 4 + r] + bout_r;
                    if (fabsf(pred - xr) > 0.1f) x0 = pred;
                }
                float4 wz = w04[jj];
                float gi = w4g[0] + wz.x * x0;
                float gF = w4g[1] + wz.y * x0;
                float gg = w4g[2] + wz.z * x0;
                float go = w4g[3] + wz.w * x0;
                float iv = sigmoidf_(gi);
                float fv = sigmoidf_(gF);
                float gv = tanhf(gg);
                float ov = sigmoidf_(go);
                c_r = fv * c_r + iv * gv;
                float hn = ov * tanhf(c_r);

                int kg = (int)rank * JH + jj;
                int kp = kg >> 1;
                int o2 = kp / QK, kw = kp - o2 * QK;
                uint32_t hoff = (uint32_t)(OFF_HQ + nxt * HBUF + o2 * 368
                                           + kw * 32 + r * 8 + (kg & 1) * 4);
                *(float*)(smem + hoff) = hn;
                st_remote_f32(smem_b + hoff, peer, hn);
                p = hn * wo[jj];
            }
            // ---- per-warp pred partial (sum over jj groups in warp) ----
            if (wid == 20) {
                p += __shfl_xor_sync(0xffffu, p, 8);
            } else {
                p += __shfl_xor_sync(0xffffffffu, p, 8);
                p += __shfl_xor_sync(0xffffffffu, p, 16);
            }
            if (lane < 4) {
                int r = (lane >> 1) | ((lane & 1) << 1);
                pwf[(cur * 21 + wid) * 4 + r] = p;
            }
        } else {
            // ---- spare threads: pred/flag outputs + x prefetch ----
            int sp = tid - CT;
            if (sp < 4) {
                int r = sp, row = row0 + r;
                if (t > 0) {
                    float pred = prf[nxt * 4 + r] + prf[8 + nxt * 4 + r] + bout_r;
                    float xr = xqf[(cur * 8 + 0) * 4 + r];
                    float flag = (fabsf(pred - xr) > 0.1f) ? 1.f : 0.f;
                    if (rank == 0) {
                        out[(size_t)row * Tt + (t - 1)] = pred;
                        out[(size_t)Bb * Tt + (size_t)row * Tt + t] = flag;
                    }
                } else if (rank == 0) {
                    out[(size_t)Bb * Tt + (size_t)row * Tt] = 0.f;
                }
            } else if (sp >= 8 && (t + 1 < Tt)) {
                int i = sp - 8;
#pragma unroll
                for (int r = 0; r < 4; r++)
                    xqf[(nxt * 8 + i) * 4 + r] =
                        x[((size_t)((row0 + r) * Tt + t + 1)) * 8 + i];
            }
        }
        __syncthreads();   // h local + pw published; remote STS drained

        // ---- pred partial reduction + cross-CTA signal (4 lanes of warp 0) ----
        if (tid < 4) {
            float s = 0.f;
#pragma unroll
            for (int w = 0; w < 21; w++) s += pwf[(cur * 21 + w) * 4 + tid];
            prf[cur * 4 + tid] = s;
            st_remote_f32(smem_b + (uint32_t)(OFF_PR + 32 + (cur * 4 + tid) * 4), peer, s);
            mbar_arrive_peer(mbar_b + (uint32_t)(cur * 8), peer);
        }
    }

    // ---- tail: final prediction at column Tt-1 ----
    mbar_wait(mbar_b + (uint32_t)(((Tt - 1) & 1) * 8), (uint32_t)(((Tt - 1) >> 1) & 1));
    if (rank == 0 && tid < 4) {
        int par = (Tt - 1) & 1;
        float pred = prf[par * 4 + tid] + prf[8 + par * 4 + tid] + bout_r;
        out[(size_t)(row0 + tid) * Tt + (Tt - 1)] = pred;
    }
}

extern "C" void kernel_launch(void* const* d_in, const int* in_sizes, int n_in,
                              void* d_out, int out_size) {
    (void)in_sizes; (void)n_in; (void)out_size;
    cudaFuncSetAttribute(lstm_anom_kernel,
                         cudaFuncAttributeMaxDynamicSharedMemorySize, SMEM_TOTAL);
    lstm_anom_kernel<<<NCTA, NTH, SMEM_TOTAL>>>(
        (const float*)d_in[0],   // x
        (const float*)d_in[1],   // W_ih
        (const float*)d_in[2],   // W_hh
        (const float*)d_in[3],   // b_ih
        (const float*)d_in[4],   // b_hh
        (const float*)d_in[5],   // W_out
        (const float*)d_in[6],   // b_out
        (float*)d_out);
}

// round 6
// speedup vs baseline: 1.4888x; 1.4888x over previous
#include <cuda_runtime.h>
#include <cstdint>
#include <math.h>

// Problem constants
#define Bb   256
#define Tt   1024
#define Hh   164
#define JH   82          // hidden slice per CTA (M-split across 2-CTA cluster)
#define KHP  41          // k-pairs per k-half
#define RKK  22          // k-pairs in registers per thread
#define SKK  (KHP - RKK) // 19 k-pairs in smem
#define NTH  384         // 12 warps: wg0 = warps 0-5 (local k), wg1 = warps 6-11 (peer k)
#define NCTA 128         // 64 clusters x 2
#define HBUF 2624        // 82 k-pairs * 32B per parity

// shared memory layout (bytes)
#define OFF_WSM   0
#define SZ_WSM    (SKK * 328 * 16)          // 99712: Wsm2[kks][wg*164+g] = (wA,wB)
#define OFF_HQ    (OFF_WSM + SZ_WSM)        // 99712
#define SZ_HQ     (2 * HBUF)                // 5248
#define OFF_GB    (OFF_HQ + SZ_HQ)          // 104960
#define SZ_GB     (2 * 2 * 164 * 16)        // 10496: gb4[(wg*2+ab)*164+g]
#define OFF_PW    (OFF_GB + SZ_GB)          // 115456
#define SZ_PW     (2 * 2 * 11 * 16)         // 704: pwf[par][side][w][r]
#define OFF_XQ    (OFF_PW + SZ_PW)          // 116160
#define SZ_XQ     (2 * 8 * 16)              // 256
#define OFF_WIH   (OFF_XQ + SZ_XQ)          // 116416
#define SZ_WIH    (14 * 164 * 4)            // 9184: wihs[(ab*7+i-1)*164+g]
#define OFF_W04   (OFF_WIH + SZ_WIH)        // 125600
#define SZ_W04    (82 * 16)                 // w_ih[:,0] per gate float4 per jj
#define OFF_WO    (OFF_W04 + SZ_W04)        // 126912
#define SZ_WO     (82 * 4)
#define OFF_B2    (OFF_WO + SZ_WO)          // 127240: (biasA,biasB) float2 per g
#define SZ_B2     (164 * 8)
#define OFF_MBAR  (OFF_B2 + SZ_B2)          // 128552
#define SMEM_TOTAL (OFF_MBAR + 16)

typedef unsigned long long ull;

__device__ __forceinline__ float sigmoidf_(float v) {
    return 1.0f / (1.0f + expf(-v));
}
__device__ __forceinline__ ull pack2_(float a, float b) {
    ull r; asm("mov.b64 %0, {%1, %2};" : "=l"(r) : "f"(a), "f"(b)); return r;
}
__device__ __forceinline__ void unpack2_(ull v, float& a, float& b) {
    asm("mov.b64 {%0, %1}, %2;" : "=f"(a), "=f"(b) : "l"(v));
}
__device__ __forceinline__ void fma2_(ull& acc, ull a, ull b) {
    asm("fma.rn.f32x2 %0, %1, %2, %0;" : "+l"(acc) : "l"(a), "l"(b));
}
__device__ __forceinline__ void st_remote_f32(uint32_t local_addr, uint32_t peer, float v) {
    uint32_t ra;
    asm("mapa.shared::cluster.u32 %0, %1, %2;" : "=r"(ra) : "r"(local_addr), "r"(peer));
    asm volatile("st.shared::cluster.f32 [%0], %1;" :: "r"(ra), "f"(v) : "memory");
}
__device__ __forceinline__ void mbar_arrive_peer(uint32_t local_mbar, uint32_t peer) {
    asm volatile(
        "{\n\t.reg .b32 ra;\n\t"
        "mapa.shared::cluster.u32 ra, %0, %1;\n\t"
        "mbarrier.arrive.release.cluster.shared::cluster.b64 _, [ra];\n\t}"
        :: "r"(local_mbar), "r"(peer) : "memory");
}
__device__ __forceinline__ void mbar_wait(uint32_t mbar, uint32_t parity) {
    uint32_t done;
    asm volatile(
        "{\n\t.reg .pred p;\n\t"
        "mbarrier.try_wait.parity.acquire.cluster.shared::cta.b64 p, [%1], %2;\n\t"
        "selp.b32 %0, 1, 0, p;\n\t}"
        : "=r"(done) : "r"(mbar), "r"(parity) : "memory");
    while (!done) {
        asm volatile(
            "{\n\t.reg .pred p;\n\t"
            "mbarrier.try_wait.parity.acquire.cluster.shared::cta.b64 p, [%1], %2, 0x989680;\n\t"
            "selp.b32 %0, 1, 0, p;\n\t}"
            : "=r"(done) : "r"(mbar), "r"(parity) : "memory");
    }
}

extern "C" __global__ void __launch_bounds__(NTH, 1) __cluster_dims__(2, 1, 1)
lstm_anom_kernel(const float* __restrict__ x,
                 const float* __restrict__ Wih,
                 const float* __restrict__ Whh,
                 const float* __restrict__ bih,
                 const float* __restrict__ bhh,
                 const float* __restrict__ Wout,
                 const float* __restrict__ bout,
                 float* __restrict__ out)
{
    extern __shared__ char smem[];
    ulonglong2* Wsm2 = (ulonglong2*)(smem + OFF_WSM);
    float4* gb4  = (float4*)(smem + OFF_GB);
    const float* gbf = (const float*)(smem + OFF_GB);
    float*  pwf  = (float*)(smem + OFF_PW);
    float*  xqf  = (float*)(smem + OFF_XQ);
    float*  wihs = (float*)(smem + OFF_WIH);
    float4* w04  = (float4*)(smem + OFF_W04);
    float*  wo   = (float*)(smem + OFF_WO);
    float2* b2   = (float2*)(smem + OFF_B2);

    const int tid       = threadIdx.x;
    const uint32_t rank = (uint32_t)(blockIdx.x & 1);
    const uint32_t peer = rank ^ 1u;
    const int cluster   = blockIdx.x >> 1;
    const int row0      = cluster * 4;

    const uint32_t smem_b = (uint32_t)__cvta_generic_to_shared(smem);
    const uint32_t mbar_b = smem_b + OFF_MBAR;

    // ---------- roles ----------
    const int wg = (tid >= 192);           // 0 = local-k warps (0-5), 1 = peer-k (6-11)
    const int g  = tid - wg * 192;         // gate-row-pair id; active iff g < 164
    const bool active = (g < 164);
    const int kr  = wg ? (int)(rank ^ 1u) : (int)rank;   // which global k-half
    const int kp0 = kr * KHP;

    // ---------- one-time init ----------
    ull wregA[RKK], wregB[RKK];
    if (active) {
        int gt  = g / JH;
        int jj0 = g - gt * JH;
        int RA  = gt * Hh + (int)rank * JH + jj0;        // gate i (gt0) / f (gt1)
        int RB  = (gt + 2) * Hh + (int)rank * JH + jj0;  // gate g / o
        const ull* wrA = (const ull*)(Whh + (size_t)RA * Hh) + kp0;
        const ull* wrB = (const ull*)(Whh + (size_t)RB * Hh) + kp0;
#pragma unroll
        for (int kk = 0; kk < RKK; kk++) { wregA[kk] = wrA[kk]; wregB[kk] = wrB[kk]; }
        for (int kk = RKK; kk < KHP; kk++)
            Wsm2[(kk - RKK) * 328 + wg * 164 + g] = make_ulonglong2(wrA[kk], wrB[kk]);
        if (wg == 0) {
#pragma unroll
            for (int i = 1; i < 8; i++) {
                wihs[(0 * 7 + i - 1) * 164 + g] = Wih[RA * 8 + i];
                wihs[(1 * 7 + i - 1) * 164 + g] = Wih[RB * 8 + i];
            }
            b2[g] = make_float2(bih[RA] + bhh[RA], bih[RB] + bhh[RB]);
        }
    }
    if (tid < JH) {
        int base = (int)rank * JH + tid;
        w04[tid] = make_float4(Wih[(0 * Hh + base) * 8], Wih[(1 * Hh + base) * 8],
                               Wih[(2 * Hh + base) * 8], Wih[(3 * Hh + base) * 8]);
        wo[tid] = Wout[base];
    }
    for (int idx = tid; idx < (SZ_HQ / 4); idx += NTH)
        ((float*)(smem + OFF_HQ))[idx] = 0.f;
    for (int idx = tid; idx < (SZ_PW / 4); idx += NTH) pwf[idx] = 0.f;
    if (tid < 32) {
        int i = tid >> 2, r = tid & 3;
        xqf[(0 * 8 + i) * 4 + r] = x[((size_t)((row0 + r) * Tt)) * 8 + i];
    }
    if (tid == 0) {
        asm volatile("mbarrier.init.shared.b64 [%0], 1;" :: "r"(mbar_b) : "memory");
        asm volatile("mbarrier.init.shared.b64 [%0], 1;" :: "r"(mbar_b + 8) : "memory");
    }
    const float bout_r = bout[0];
    float c_r = 0.f;                  // per (jj, r) for tid < 328
    const int jj = tid >> 2, rr = tid & 3;
    const int wid = tid >> 5, lane = tid & 31;

    __syncthreads();
    asm volatile("barrier.cluster.arrive.aligned;" ::: "memory");
    asm volatile("barrier.cluster.wait.aligned;" ::: "memory");

    for (int t = 0; t < Tt; ++t) {
        const int cur = t & 1;
        const int nxt = cur ^ 1;

        // only peer-k warps (6-11) wait: spares + peer-half GEMV need peer data.
        if (wg && t)
            mbar_wait(mbar_b + (uint32_t)(((t - 1) & 1) * 8), (uint32_t)(((t - 1) >> 1) & 1));

        if (active) {
            // ---- GEMV over this thread's k-half ----
            ull accA[4], accB[4];
            if (wg == 0) {
                float2 bb = b2[g];
                float a0 = bb.x, a1 = bb.x, a2 = bb.x, a3 = bb.x;
                float b0 = bb.y, b1 = bb.y, b2v = bb.y, b3 = bb.y;
                const float4* xv4 = (const float4*)(smem + OFF_XQ + cur * 128);
#pragma unroll
                for (int i = 1; i < 8; i++) {
                    float4 xv = xv4[i];
                    float wA = wihs[(0 * 7 + i - 1) * 164 + g];
                    float wB = wihs[(1 * 7 + i - 1) * 164 + g];
                    a0 += wA * xv.x; a1 += wA * xv.y; a2 += wA * xv.z; a3 += wA * xv.w;
                    b0 += wB * xv.x; b1 += wB * xv.y; b2v += wB * xv.z; b3 += wB * xv.w;
                }
                accA[0] = pack2_(a0, 0.f); accA[1] = pack2_(a1, 0.f);
                accA[2] = pack2_(a2, 0.f); accA[3] = pack2_(a3, 0.f);
                accB[0] = pack2_(b0, 0.f); accB[1] = pack2_(b1, 0.f);
                accB[2] = pack2_(b2v, 0.f); accB[3] = pack2_(b3, 0.f);
            } else {
#pragma unroll
                for (int s = 0; s < 4; s++) { accA[s] = 0ull; accB[s] = 0ull; }
            }
            const ulonglong2* hp =
                (const ulonglong2*)(smem + OFF_HQ + cur * HBUF + kp0 * 32);
#pragma unroll
            for (int kk = 0; kk < RKK; kk++) {
                ulonglong2 h01 = hp[2 * kk];
                ulonglong2 h23 = hp[2 * kk + 1];
                fma2_(accA[0], wregA[kk], h01.x); fma2_(accB[0], wregB[kk], h01.x);
                fma2_(accA[1], wregA[kk], h01.y); fma2_(accB[1], wregB[kk], h01.y);
                fma2_(accA[2], wregA[kk], h23.x); fma2_(accB[2], wregB[kk], h23.x);
                fma2_(accA[3], wregA[kk], h23.y); fma2_(accB[3], wregB[kk], h23.y);
            }
#pragma unroll
            for (int kk = RKK; kk < KHP; kk++) {
                ulonglong2 w2 = Wsm2[(kk - RKK) * 328 + wg * 164 + g];
                ulonglong2 h01 = hp[2 * kk];
                ulonglong2 h23 = hp[2 * kk + 1];
                fma2_(accA[0], w2.x, h01.x); fma2_(accB[0], w2.y, h01.x);
                fma2_(accA[1], w2.x, h01.y); fma2_(accB[1], w2.y, h01.y);
                fma2_(accA[2], w2.x, h23.x); fma2_(accB[2], w2.y, h23.x);
                fma2_(accA[3], w2.x, h23.y); fma2_(accB[3], w2.y, h23.y);
            }
            float lo, hi;
            float4 vA, vB;
            unpack2_(accA[0], lo, hi); vA.x = lo + hi;
            unpack2_(accA[1], lo, hi); vA.y = lo + hi;
            unpack2_(accA[2], lo, hi); vA.z = lo + hi;
            unpack2_(accA[3], lo, hi); vA.w = lo + hi;
            unpack2_(accB[0], lo, hi); vB.x = lo + hi;
            unpack2_(accB[1], lo, hi); vB.y = lo + hi;
            unpack2_(accB[2], lo, hi); vB.z = lo + hi;
            unpack2_(accB[3], lo, hi); vB.w = lo + hi;
            gb4[(wg * 2 + 0) * 164 + g] = vA;
            gb4[(wg * 2 + 1) * 164 + g] = vB;
        } else if (tid >= 356) {
            // ---- spares (warp 11 tail): pred finalize, anomaly fix, x prefetch ----
            int sp = tid - 356;
            if (sp < 4) {
                int r = sp, row = row0 + r;
                if (t > 0) {
                    float pred = bout_r;
#pragma unroll
                    for (int w = 0; w < 11; w++) {
                        pred += pwf[((nxt * 2 + 0) * 11 + w) * 4 + r];
                        pred += pwf[((nxt * 2 + 1) * 11 + w) * 4 + r];
                    }
                    float x0raw = xqf[(cur * 8 + 0) * 4 + r];
                    float flag = 0.f, x0 = x0raw;
                    if (fabsf(pred - x0raw) > 0.1f) { x0 = pred; flag = 1.f; }
                    xqf[(cur * 8 + 0) * 4 + r] = x0;
                    if (rank == 0) {
                        out[(size_t)row * Tt + (t - 1)] = pred;
                        out[(size_t)Bb * Tt + (size_t)row * Tt + t] = flag;
                    }
                } else if (rank == 0) {
                    out[(size_t)Bb * Tt + (size_t)row * Tt] = 0.f;
                }
            } else if (sp >= 8 && sp < 16 && (t + 1 < Tt)) {
                int i = sp - 8;
#pragma unroll
                for (int r = 0; r < 4; r++)
                    xqf[(nxt * 8 + i) * 4 + r] =
                        x[((size_t)((row0 + r) * Tt + t + 1)) * 8 + i];
            }
        }
        __syncthreads();   // gate partials + fixed x0 published

        // ---- activation, state update, h exchange, pred partials (tid < 328) ----
        if (tid < 328) {
            float x0 = xqf[(cur * 8 + 0) * 4 + rr];
            float4 wz = w04[jj];
            float gi = gbf[((0 * 2 + 0) * 164 + jj) * 4 + rr]
                     + gbf[((1 * 2 + 0) * 164 + jj) * 4 + rr] + wz.x * x0;
            float gF = gbf[((0 * 2 + 0) * 164 + jj + 82) * 4 + rr]
                     + gbf[((1 * 2 + 0) * 164 + jj + 82) * 4 + rr] + wz.y * x0;
            float gg = gbf[((0 * 2 + 1) * 164 + jj) * 4 + rr]
                     + gbf[((1 * 2 + 1) * 164 + jj) * 4 + rr] + wz.z * x0;
            float go = gbf[((0 * 2 + 1) * 164 + jj + 82) * 4 + rr]
                     + gbf[((1 * 2 + 1) * 164 + jj + 82) * 4 + rr] + wz.w * x0;
            float iv = sigmoidf_(gi);
            float fv = sigmoidf_(gF);
            float gv = tanhf(gg);
            float ov = sigmoidf_(go);
            c_r = fv * c_r + iv * gv;
            float hn = ov * tanhf(c_r);

            int kg = (int)rank * JH + jj;
            uint32_t hoff = (uint32_t)(OFF_HQ + nxt * HBUF
                                       + (kg >> 1) * 32 + rr * 8 + (kg & 1) * 4);
            *(float*)(smem + hoff) = hn;
            st_remote_f32(smem_b + hoff, peer, hn);

            float p = hn * wo[jj];
            if (wid < 10) {
                p += __shfl_xor_sync(0xffffffffu, p, 16);
                p += __shfl_xor_sync(0xffffffffu, p, 8);
                p += __shfl_xor_sync(0xffffffffu, p, 4);
            } else {
                p += __shfl_xor_sync(0xffu, p, 4);
            }
            if (lane < 4) {
                uint32_t po0 = (uint32_t)(OFF_PW + (((cur * 2 + 0) * 11 + wid) * 4 + lane) * 4);
                uint32_t po1 = (uint32_t)(OFF_PW + (((cur * 2 + 1) * 11 + wid) * 4 + lane) * 4);
                *(float*)(smem + po0) = p;            // own side
                st_remote_f32(smem_b + po1, peer, p); // peer's side-1
            }
        }
        __syncthreads();   // local h/pw writes visible; remote stores issued

        if (tid == 0) mbar_arrive_peer(mbar_b + (uint32_t)(cur * 8), peer);
    }

    // ---- tail: final prediction at column Tt-1 ----
    mbar_wait(mbar_b + (uint32_t)(((Tt - 1) & 1) * 8), (uint32_t)(((Tt - 1) >> 1) & 1));
    if (rank == 0 && tid < 4) {
        int par = (Tt - 1) & 1;
        float pred = bout_r;
#pragma unroll
        for (int w = 0; w < 11; w++) {
            pred += pwf[((par * 2 + 0) * 11 + w) * 4 + tid];
            pred += pwf[((par * 2 + 1) * 11 + w) * 4 + tid];
        }
        out[(size_t)(row0 + tid) * Tt + (Tt - 1)] = pred;
    }
}

extern "C" void kernel_launch(void* const* d_in, const int* in_sizes, int n_in,
                              void* d_out, int out_size) {
    (void)in_sizes; (void)n_in; (void)out_size;
    cudaFuncSetAttribute(lstm_anom_kernel,
                         cudaFuncAttributeMaxDynamicSharedMemorySize, SMEM_TOTAL);
    lstm_anom_kernel<<<NCTA, NTH, SMEM_TOTAL>>>(
        (const float*)d_in[0],   // x
        (const float*)d_in[1],   // W_ih
        (const float*)d_in[2],   // W_hh
        (const float*)d_in[3],   // b_ih
        (const float*)d_in[4],   // b_hh
        (const float*)d_in[5],   // W_out
        (const float*)d_in[6],   // b_out
        (float*)d_out);
}